// round 2
// baseline (speedup 1.0000x reference)
#include <cuda_runtime.h>

#define Nn 128
#define Tn 2048
#define Bn 64

// Precomputed exp-domain constants (written by prep_kernel each launch).
__device__ __align__(16) float g_ET[Nn * Nn];   // ET[j*N + i] = forbidden ? 0 : exp(trans[i][j])
__device__ float g_stexp[Nn];                   // exp(start) or 0
__device__ float g_enexp[Nn];                   // exp(end) or 0

__global__ void prep_kernel(const float* __restrict__ trans,
                            const float* __restrict__ st,
                            const float* __restrict__ en,
                            const int* __restrict__ ftr,
                            const int* __restrict__ fst,
                            const int* __restrict__ fen,
                            float* __restrict__ out)
{
    int idx = blockIdx.x * blockDim.x + threadIdx.x;
    if (idx < Nn * Nn) {
        int j = idx >> 7;
        int i = idx & (Nn - 1);
        g_ET[idx] = ftr[i * Nn + j] ? 0.0f : expf(trans[i * Nn + j]);
    }
    if (idx < Nn) {
        g_stexp[idx] = fst[idx] ? 0.0f : expf(st[idx]);
        g_enexp[idx] = fen[idx] ? 0.0f : expf(en[idx]);
    }
    if (idx < Bn) out[idx] = 0.0f;
}

// Packed fp32x2 FMA (Blackwell): 2 fp32 FMAs per instruction on the fma pipe.
__device__ __forceinline__ unsigned long long ffma2(unsigned long long a,
                                                    unsigned long long b,
                                                    unsigned long long c)
{
    unsigned long long d;
    asm("fma.rn.f32x2 %0, %1, %2, %3;" : "=l"(d) : "l"(a), "l"(b), "l"(c));
    return d;
}

__device__ __forceinline__ float unpack_add(unsigned long long a)
{
    float lo, hi;
    asm("mov.b64 {%0, %1}, %2;" : "=f"(lo), "=f"(hi) : "l"(a));
    return lo + hi;
}

// One CRF step. Uses/updates: cur, v, Sexp, e_pend, inv_pend. Prefetches t+4.
#define STEP(TSTEP, EMV, TGV)                                                   \
    {                                                                           \
        const float emc = EMV;                                                  \
        const int tgc = TGV;                                                    \
        const int tp = (TSTEP) + 4;                                             \
        if (tp < Tn) { EMV = emrow[tp * Nn]; TGV = tgrow[tp * Nn]; }            \
        const ulonglong2* uvec = (const ulonglong2*)(&U[cur][h64]);             \
        unsigned long long a0 = 0ull, a1 = 0ull, a2 = 0ull, a3 = 0ull;          \
        _Pragma("unroll")                                                       \
        for (int k = 0; k < 16; k += 2) {                                       \
            ulonglong2 u2 = uvec[k];                                            \
            a0 = ffma2(Ep[k].x, u2.x, a0);                                      \
            a1 = ffma2(Ep[k].y, u2.y, a1);                                      \
            ulonglong2 u3 = uvec[k + 1];                                        \
            a2 = ffma2(Ep[k + 1].x, u3.x, a2);                                  \
            a3 = ffma2(Ep[k + 1].y, u3.y, a3);                                  \
        }                                                                       \
        float s = (unpack_add(a0) + unpack_add(a1))                             \
                + (unpack_add(a2) + unpack_add(a3));                            \
        s += __shfl_xor_sync(0xffffffffu, s, 1);                                \
        float p = __expf(emc);                                                  \
        if (sup && tgc == 0) p = 0.0f;                                          \
        v = s * p * inv_pend;                                                   \
        Sexp += e_pend;                                                         \
        unsigned int wmu = __reduce_max_sync(0xffffffffu, __float_as_uint(v));  \
        const int par = (TSTEP) & 1;                                            \
        if (lane == 0) wmaxbuf[par][warp] = wmu;                                \
        const int nxt = cur ^ 1;                                                \
        if (h == 0) U[nxt][j] = v;                                              \
        __syncthreads();                                                        \
        unsigned int rm = wmaxbuf[par][0];                                      \
        _Pragma("unroll")                                                       \
        for (int w = 1; w < 8; w++) rm = max(rm, wmaxbuf[par][w]);              \
        e_pend = (int)(rm >> 23) - 127;                                         \
        inv_pend = __int_as_float((127 - e_pend) << 23);                        \
        cur = nxt;                                                              \
        if ((TSTEP) == Lm1) goto finalize;                                      \
    }

__global__ void __launch_bounds__(256, 1)
crf_kernel(const float* __restrict__ em,
           const int* __restrict__ mask,
           const int* __restrict__ tgt,
           float* __restrict__ out)
{
    __shared__ __align__(16) float U[2][Nn];   // scaled exp(alpha), double-buffered
    __shared__ unsigned int wmaxbuf[2][8];     // per-warp maxes (float-as-uint), double-buffered
    __shared__ float zpart[8];
    __shared__ int s_len;

    const int tid = threadIdx.x;
    const int bidx = blockIdx.x;        // 128 blocks: (channel, batch)
    const int c = bidx & 1;             // 0 = supervised, 1 = partition
    const int b = bidx >> 1;
    const int j = tid >> 1;             // output state column
    const int h = tid & 1;              // which half of the i-range
    const int h64 = h << 6;
    const int warp = tid >> 5;
    const int lane = tid & 31;
    const bool sup = (c == 0);

    // ---- sequence length from mask (int32 bools) ----
    if (tid == 0) s_len = 0;
    __syncthreads();
    {
        int cnt = 0;
        const int* mrow = mask + b * Tn;
        for (int k = tid; k < Tn; k += 256) cnt += (mrow[k] != 0) ? 1 : 0;
        #pragma unroll
        for (int o = 16; o; o >>= 1) cnt += __shfl_xor_sync(0xffffffffu, cnt, o);
        if (lane == 0) atomicAdd(&s_len, cnt);
    }

    // ---- load this thread's half-column of E into registers (32 packed pairs) ----
    ulonglong2 Ep[16];
    {
        const ulonglong2* ecol = (const ulonglong2*)(g_ET + j * Nn + h64);
        #pragma unroll
        for (int k = 0; k < 16; k++) Ep[k] = ecol[k];
    }
    const float enj = g_enexp[j];
    const float stj = g_stexp[j];

    const float* emrow = em + (b * Tn) * Nn + j;
    const int*   tgrow = tgt + (b * Tn) * Nn + j;

    __syncthreads();
    int L = s_len;
    int Lm1 = L - 1;
    if (Lm1 < 0) Lm1 = 0;
    if (Lm1 > Tn - 1) Lm1 = Tn - 1;

    float v;
    int Sexp = 0;
    int e_pend;
    float inv_pend;
    int cur = 0;

    // ---- t = 0: alpha0 = emissions(0) + start ----
    {
        float em0v = emrow[0];
        int tg0v = tgrow[0];
        float p = __expf(em0v);
        if (sup && tg0v == 0) p = 0.0f;
        v = p * stj;
        unsigned int wmu = __reduce_max_sync(0xffffffffu, __float_as_uint(v));
        if (lane == 0) wmaxbuf[0][warp] = wmu;
        if (h == 0) U[0][j] = v;
        __syncthreads();
        unsigned int rm = wmaxbuf[0][0];
        #pragma unroll
        for (int w = 1; w < 8; w++) rm = max(rm, wmaxbuf[0][w]);
        e_pend = (int)(rm >> 23) - 127;
        inv_pend = __int_as_float((127 - e_pend) << 23);
    }
    if (Lm1 == 0) goto finalize;

    // ---- main scan, 4-deep software-pipelined emission/target prefetch ----
    {
        float em0, em1, em2, em3;
        int tg0, tg1, tg2, tg3;
        em0 = emrow[1 * Nn]; tg0 = tgrow[1 * Nn];
        em1 = emrow[2 * Nn]; tg1 = tgrow[2 * Nn];
        em2 = emrow[3 * Nn]; tg2 = tgrow[3 * Nn];
        em3 = emrow[4 * Nn]; tg3 = tgrow[4 * Nn];

        for (int base = 1; base < Tn; base += 4) {
            STEP(base + 0, em0, tg0)
            STEP(base + 1, em1, tg1)
            STEP(base + 2, em2, tg2)
            STEP(base + 3, em3, tg3)
        }
    }

finalize:
    // z = Sexp*ln2 + log(sum_j v_j * exp(end_j));  loss = z1 - z0
    {
        float contrib = (h == 0) ? v * enj : 0.0f;
        #pragma unroll
        for (int o = 16; o; o >>= 1) contrib += __shfl_xor_sync(0xffffffffu, contrib, o);
        if (lane == 0) zpart[warp] = contrib;
        __syncthreads();
        if (tid == 0) {
            float zs = 0.0f;
            #pragma unroll
            for (int w = 0; w < 8; w++) zs += zpart[w];
            double z = (double)Sexp * 0.6931471805599453 + (double)logf(zs);
            float add = (float)(sup ? -z : z);
            atomicAdd(out + b, add);   // exactly 2 adds per b: commutative -> deterministic
        }
    }
}

#undef STEP

extern "C" void kernel_launch(void* const* d_in, const int* in_sizes, int n_in,
                              void* d_out, int out_size)
{
    const float* em    = (const float*)d_in[0];
    const int*   mask  = (const int*)d_in[1];
    const int*   tgt   = (const int*)d_in[2];
    const float* trans = (const float*)d_in[3];
    const float* st    = (const float*)d_in[4];
    const float* en    = (const float*)d_in[5];
    const int*   ftr   = (const int*)d_in[6];
    const int*   fst   = (const int*)d_in[7];
    const int*   fen   = (const int*)d_in[8];
    float* out = (float*)d_out;

    prep_kernel<<<64, 256>>>(trans, st, en, ftr, fst, fen, out);
    crf_kernel<<<2 * Bn, 256>>>(em, mask, tgt, out);
}

// round 3
// speedup vs baseline: 1.3866x; 1.3866x over previous
#include <cuda_runtime.h>

#define Nn 128
#define Tn 2048
#define Bn 64

// Precomputed exp-domain constants (written by prep_kernel each launch).
__device__ __align__(16) float g_ET[Nn * Nn];   // ET[j*N + i] = forbidden ? 0 : exp(trans[i][j])
__device__ float g_stexp[Nn];                   // exp(start) or 0
__device__ float g_enexp[Nn];                   // exp(end) or 0

__global__ void prep_kernel(const float* __restrict__ trans,
                            const float* __restrict__ st,
                            const float* __restrict__ en,
                            const int* __restrict__ ftr,
                            const int* __restrict__ fst,
                            const int* __restrict__ fen,
                            float* __restrict__ out)
{
    int idx = blockIdx.x * blockDim.x + threadIdx.x;
    if (idx < Nn * Nn) {
        int j = idx >> 7;
        int i = idx & (Nn - 1);
        g_ET[idx] = ftr[i * Nn + j] ? 0.0f : expf(trans[i * Nn + j]);
    }
    if (idx < Nn) {
        g_stexp[idx] = fst[idx] ? 0.0f : expf(st[idx]);
        g_enexp[idx] = fen[idx] ? 0.0f : expf(en[idx]);
    }
    if (idx < Bn) out[idx] = 0.0f;
}

// Packed fp32x2 ops (Blackwell): 2 fp32 FMAs/ADDs per instruction on the fma pipe.
__device__ __forceinline__ unsigned long long ffma2(unsigned long long a,
                                                    unsigned long long b,
                                                    unsigned long long c)
{
    unsigned long long d;
    asm("fma.rn.f32x2 %0, %1, %2, %3;" : "=l"(d) : "l"(a), "l"(b), "l"(c));
    return d;
}

__device__ __forceinline__ unsigned long long addf2(unsigned long long a,
                                                    unsigned long long b)
{
    unsigned long long d;
    asm("add.rn.f32x2 %0, %1, %2;" : "=l"(d) : "l"(a), "l"(b));
    return d;
}

__device__ __forceinline__ float unpack_add(unsigned long long a)
{
    float lo, hi;
    asm("mov.b64 {%0, %1}, %2;" : "=f"(lo), "=f"(hi) : "l"(a));
    return lo + hi;
}

// One CRF step, full 128-dim inner product per thread.
// MODE: 0 = plain, 1 = apply pending renorm scale, 2 = compute new block max.
// RB/WB: compile-time read/write U buffer indices.
#define STEP(TSTEP, EMV, TGV, RB, WB, MODE)                                       \
    {                                                                             \
        float p = __expf(EMV);                                                    \
        if (sup && (TGV) == 0) p = 0.0f;                                          \
        const int tp = (TSTEP) + 4;                                               \
        if (tp < Tn) { EMV = emrow[tp * Nn]; TGV = tgrow[tp * Nn]; }              \
        const ulonglong2* uvec = (const ulonglong2*)U[RB];                        \
        unsigned long long a0 = 0ull, a1 = 0ull, a2 = 0ull, a3 = 0ull;            \
        unsigned long long a4 = 0ull, a5 = 0ull, a6 = 0ull, a7 = 0ull;            \
        _Pragma("unroll")                                                         \
        for (int k = 0; k < 32; k += 4) {                                         \
            ulonglong2 u0 = uvec[k];                                              \
            ulonglong2 u1 = uvec[k + 1];                                          \
            ulonglong2 u2 = uvec[k + 2];                                          \
            ulonglong2 u3 = uvec[k + 3];                                          \
            a0 = ffma2(Ep[k].x,     u0.x, a0);                                    \
            a1 = ffma2(Ep[k].y,     u0.y, a1);                                    \
            a2 = ffma2(Ep[k + 1].x, u1.x, a2);                                    \
            a3 = ffma2(Ep[k + 1].y, u1.y, a3);                                    \
            a4 = ffma2(Ep[k + 2].x, u2.x, a4);                                    \
            a5 = ffma2(Ep[k + 2].y, u2.y, a5);                                    \
            a6 = ffma2(Ep[k + 3].x, u3.x, a6);                                    \
            a7 = ffma2(Ep[k + 3].y, u3.y, a7);                                    \
        }                                                                         \
        a0 = addf2(a0, a1); a2 = addf2(a2, a3);                                   \
        a4 = addf2(a4, a5); a6 = addf2(a6, a7);                                   \
        a0 = addf2(a0, a2); a4 = addf2(a4, a6);                                   \
        a0 = addf2(a0, a4);                                                       \
        float s = unpack_add(a0);                                                 \
        if ((MODE) == 1) { v = s * p * inv_pend; Sexp += e_pend; }                \
        else             { v = s * p; }                                           \
        U[WB][j] = v;                                                             \
        if ((MODE) == 2) {                                                        \
            unsigned int wmu = __reduce_max_sync(0xffffffffu, __float_as_uint(v));\
            if (lane == 0) wmaxbuf[warp] = wmu;                                   \
        }                                                                         \
        __syncthreads();                                                          \
        if ((MODE) == 2) {                                                        \
            unsigned int rm = max(max(wmaxbuf[0], wmaxbuf[1]),                    \
                                  max(wmaxbuf[2], wmaxbuf[3]));                   \
            e_pend = (int)(rm >> 23) - 127;                                       \
            inv_pend = __int_as_float((127 - e_pend) << 23);                      \
        }                                                                         \
        if ((TSTEP) == Lm1) goto finalize;                                        \
    }

__global__ void __launch_bounds__(128, 1)
crf_kernel(const float* __restrict__ em,
           const int* __restrict__ mask,
           const int* __restrict__ tgt,
           float* __restrict__ out)
{
    __shared__ __align__(16) float U[2][Nn];   // scaled exp(alpha), double-buffered
    __shared__ unsigned int wmaxbuf[4];        // per-warp maxes (float-as-uint)
    __shared__ float zpart[4];
    __shared__ int s_len;

    const int tid = threadIdx.x;
    const int bidx = blockIdx.x;        // 128 blocks: (channel, batch)
    const int c = bidx & 1;             // 0 = supervised, 1 = partition
    const int b = bidx >> 1;
    const int j = tid;                  // output state column (full column per thread)
    const int warp = tid >> 5;
    const int lane = tid & 31;
    const bool sup = (c == 0);

    // ---- sequence length from mask (int32 bools) ----
    if (tid == 0) s_len = 0;
    __syncthreads();
    {
        int cnt = 0;
        const int* mrow = mask + b * Tn;
        for (int k = tid; k < Tn; k += 128) cnt += (mrow[k] != 0) ? 1 : 0;
        #pragma unroll
        for (int o = 16; o; o >>= 1) cnt += __shfl_xor_sync(0xffffffffu, cnt, o);
        if (lane == 0) atomicAdd(&s_len, cnt);
    }

    // ---- load this thread's full column of E into registers (64 packed pairs) ----
    ulonglong2 Ep[32];
    {
        const ulonglong2* ecol = (const ulonglong2*)(g_ET + j * Nn);
        #pragma unroll
        for (int k = 0; k < 32; k++) Ep[k] = ecol[k];
    }
    const float enj = g_enexp[j];
    const float stj = g_stexp[j];

    const float* emrow = em + (b * Tn) * Nn + j;
    const int*   tgrow = tgt + (b * Tn) * Nn + j;

    __syncthreads();
    int L = s_len;
    int Lm1 = L - 1;
    if (Lm1 < 0) Lm1 = 0;
    if (Lm1 > Tn - 1) Lm1 = Tn - 1;

    float v;
    int Sexp = 0;
    int e_pend = 0;
    float inv_pend = 1.0f;

    // ---- t = 0: alpha0 = emissions(0) + start; writes U[0]; computes first max ----
    {
        float em0v = emrow[0];
        int tg0v = tgrow[0];
        float p = __expf(em0v);
        if (sup && tg0v == 0) p = 0.0f;
        v = p * stj;
        U[0][j] = v;
        unsigned int wmu = __reduce_max_sync(0xffffffffu, __float_as_uint(v));
        if (lane == 0) wmaxbuf[warp] = wmu;
        __syncthreads();
        unsigned int rm = max(max(wmaxbuf[0], wmaxbuf[1]),
                              max(wmaxbuf[2], wmaxbuf[3]));
        e_pend = (int)(rm >> 23) - 127;
        inv_pend = __int_as_float((127 - e_pend) << 23);
    }
    if (Lm1 == 0) goto finalize;

    // ---- main scan: 4-step unroll, renorm once per 4 steps ----
    // Step t reads U[(t+1)&1], writes U[t&1]. base = 1, 5, 9, ...
    //   base+0 (t odd):  MODE 1 (apply scale computed at previous max step)
    //   base+1, base+2:  MODE 0 (plain)
    //   base+3 (t%4==0): MODE 2 (compute new block max)
    {
        float em0, em1, em2, em3;
        int tg0, tg1, tg2, tg3;
        em0 = emrow[1 * Nn]; tg0 = tgrow[1 * Nn];
        em1 = emrow[2 * Nn]; tg1 = tgrow[2 * Nn];
        em2 = emrow[3 * Nn]; tg2 = tgrow[3 * Nn];
        em3 = emrow[4 * Nn]; tg3 = tgrow[4 * Nn];

        for (int base = 1; base < Tn; base += 4) {
            STEP(base + 0, em0, tg0, 0, 1, 1)
            STEP(base + 1, em1, tg1, 1, 0, 0)
            STEP(base + 2, em2, tg2, 0, 1, 0)
            STEP(base + 3, em3, tg3, 1, 0, 2)
        }
    }

finalize:
    // z = Sexp*ln2 + log(sum_j v_j * exp(end_j));  loss = z1 - z0
    {
        float contrib = v * enj;
        #pragma unroll
        for (int o = 16; o; o >>= 1) contrib += __shfl_xor_sync(0xffffffffu, contrib, o);
        if (lane == 0) zpart[warp] = contrib;
        __syncthreads();
        if (tid == 0) {
            float zs = (zpart[0] + zpart[1]) + (zpart[2] + zpart[3]);
            double z = (double)Sexp * 0.6931471805599453 + (double)logf(zs);
            float add = (float)(sup ? -z : z);
            atomicAdd(out + b, add);   // exactly 2 adds per b: commutative -> deterministic
        }
    }
}

#undef STEP

extern "C" void kernel_launch(void* const* d_in, const int* in_sizes, int n_in,
                              void* d_out, int out_size)
{
    const float* em    = (const float*)d_in[0];
    const int*   mask  = (const int*)d_in[1];
    const int*   tgt   = (const int*)d_in[2];
    const float* trans = (const float*)d_in[3];
    const float* st    = (const float*)d_in[4];
    const float* en    = (const float*)d_in[5];
    const int*   ftr   = (const int*)d_in[6];
    const int*   fst   = (const int*)d_in[7];
    const int*   fen   = (const int*)d_in[8];
    float* out = (float*)d_out;

    prep_kernel<<<64, 256>>>(trans, st, en, ftr, fst, fen, out);
    crf_kernel<<<2 * Bn, 128>>>(em, mask, tgt, out);
}